// round 1
// baseline (speedup 1.0000x reference)
#include <cuda_runtime.h>
#include <math.h>

#define LSEQ 2048
#define DM   1024
#define DI   2048
#define DTR  64
#define NS   16
#define NPROJ 96   // dt_rank + 2N

// ---------------- scratch (static device allocations; no cudaMalloc) --------
__device__ float g_hnorm[LSEQ * DM];       // rmsnorm output
__device__ float g_h[LSEQ * 4 * DM];       // in-proj output: [xs | res]
__device__ float g_xs[LSEQ * DI];          // silu(conv(xs))
__device__ float g_res[LSEQ * DI];         // silu(res)
__device__ float g_proj[LSEQ * NPROJ];     // [delta_low(64) | B(16) | C(16)]
__device__ float g_delta[LSEQ * DI];       // softplus(delta_low @ w_dt + b_dt)
__device__ float g_u[LSEQ * DI];           // (y + xs*D)*res  (pre out-proj)

__device__ __forceinline__ float siluf(float x) {
    return x / (1.0f + __expf(-x));
}

// ---------------- RMSNorm ---------------------------------------------------
__global__ void rmsnorm_k(const float* __restrict__ x,
                          const float* __restrict__ sc) {
    int row = blockIdx.x;
    int t = threadIdx.x;  // 256 threads, 1024 floats per row -> 1 float4 each
    float4 v = ((const float4*)(x + (size_t)row * DM))[t];
    float s = v.x * v.x + v.y * v.y + v.z * v.z + v.w * v.w;
#pragma unroll
    for (int o = 16; o; o >>= 1) s += __shfl_xor_sync(0xffffffffu, s, o);
    __shared__ float red[8];
    if ((t & 31) == 0) red[t >> 5] = s;
    __syncthreads();
    float tot = 0.f;
#pragma unroll
    for (int i = 0; i < 8; i++) tot += red[i];
    float inv = rsqrtf(tot * (1.0f / DM) + 1e-5f);
    float4 g = ((const float4*)sc)[t];
    float4 o;
    o.x = v.x * inv * g.x;
    o.y = v.y * inv * g.y;
    o.z = v.z * inv * g.z;
    o.w = v.w * inv * g.w;
    ((float4*)(g_hnorm + (size_t)row * DM))[t] = o;
}

// ---------------- classic 128x128x8 SGEMM (double-buffered smem) -----------
// C[M,N] = A[M,K](lda) @ B[K,N](ldb=N) (+ epilogue)
// EPI 0: plain   EPI 1: softplus(acc + bias[col])   EPI 2: acc + X[row,col]
template <int EPI>
__global__ void __launch_bounds__(256, 2)
sgemm_k(int M, int N, int K, int lda,
        const float* __restrict__ A, const float* __restrict__ B,
        const float* __restrict__ X, float* __restrict__ C) {
    __shared__ float As[2][8][128];
    __shared__ float Bs[2][8][128];
    int tid = threadIdx.x;
    int bx = blockIdx.x, by = blockIdx.y;
    const float* Ab = A + (size_t)(by * 128) * lda;
    const float* Bb = B + bx * 128;
    int arow = tid >> 1, acol = (tid & 1) * 4;
    int brow = tid >> 5, bcol = (tid & 31) * 4;
    int tx = (tid & 15) * 8, ty = (tid >> 4) * 8;
    float acc[8][8];
#pragma unroll
    for (int i = 0; i < 8; i++)
#pragma unroll
        for (int j = 0; j < 8; j++) acc[i][j] = 0.f;

    float4 a = *(const float4*)(Ab + (size_t)arow * lda + acol);
    float4 b = *(const float4*)(Bb + (size_t)brow * N + bcol);
    As[0][acol + 0][arow] = a.x;
    As[0][acol + 1][arow] = a.y;
    As[0][acol + 2][arow] = a.z;
    As[0][acol + 3][arow] = a.w;
    *(float4*)&Bs[0][brow][bcol] = b;
    __syncthreads();

    int buf = 0;
    for (int k0 = 0; k0 < K; k0 += 8) {
        bool more = (k0 + 8) < K;
        if (more) {
            a = *(const float4*)(Ab + (size_t)arow * lda + (k0 + 8) + acol);
            b = *(const float4*)(Bb + (size_t)(k0 + 8 + brow) * N + bcol);
        }
#pragma unroll
        for (int kk = 0; kk < 8; kk++) {
            float ar[8], br[8];
            *(float4*)ar = *(float4*)&As[buf][kk][ty];
            *(float4*)(ar + 4) = *(float4*)&As[buf][kk][ty + 4];
            *(float4*)br = *(float4*)&Bs[buf][kk][tx];
            *(float4*)(br + 4) = *(float4*)&Bs[buf][kk][tx + 4];
#pragma unroll
            for (int i = 0; i < 8; i++)
#pragma unroll
                for (int j = 0; j < 8; j++)
                    acc[i][j] = fmaf(ar[i], br[j], acc[i][j]);
        }
        if (more) {
            int nb = buf ^ 1;
            As[nb][acol + 0][arow] = a.x;
            As[nb][acol + 1][arow] = a.y;
            As[nb][acol + 2][arow] = a.z;
            As[nb][acol + 3][arow] = a.w;
            *(float4*)&Bs[nb][brow][bcol] = b;
            buf = nb;
        }
        __syncthreads();
    }

#pragma unroll
    for (int i = 0; i < 8; i++) {
        int row = by * 128 + ty + i;
#pragma unroll
        for (int j = 0; j < 8; j++) {
            int col = bx * 128 + tx + j;
            float v = acc[i][j];
            if (EPI == 1) {
                v += X[col];
                v = (v > 20.f) ? v : log1pf(__expf(v));
            } else if (EPI == 2) {
                v += X[(size_t)row * N + col];
            }
            C[(size_t)row * N + col] = v;
        }
    }
}

// ---------------- causal depthwise conv (K=4) + silu; silu(res) ------------
__global__ void conv_silu_k(const float* __restrict__ cw,
                            const float* __restrict__ cb) {
    int idx = blockIdx.x * 256 + threadIdx.x;
    int c = idx & (DI - 1);
    int l = idx >> 11;
    float acc = cb[c];
#pragma unroll
    for (int k = 0; k < 4; k++) {
        int ls = l - 3 + k;
        if (ls >= 0) acc = fmaf(g_h[(size_t)ls * (4 * DM) + c], cw[k * DI + c], acc);
    }
    g_xs[idx] = siluf(acc);
    float r = g_h[(size_t)l * (4 * DM) + DI + c];
    g_res[idx] = siluf(r);
}

// ---------------- skinny GEMM: proj[L,96] = xs[L,DI] @ w_xproj[DI,96] ------
// BM=16, BN=96, BK=32, 128 threads; thread tile 2x6
__global__ void __launch_bounds__(128) proj_k(const float* __restrict__ W) {
    __shared__ float As[32][16];
    __shared__ float Bs[32][96];
    int tid = threadIdx.x;
    int row0 = blockIdx.x * 16;
    int tx = tid & 15;   // -> cols tx*6 .. tx*6+5
    int ty = tid >> 4;   // -> rows ty*2, ty*2+1
    int arow = tid >> 3;        // 0..15
    int acol = (tid & 7) * 4;   // 0..28
    int brow = tid >> 2;        // 0..31
    int bcol = (tid & 3) * 24;  // 0,24,48,72
    float acc[2][6];
#pragma unroll
    for (int i = 0; i < 2; i++)
#pragma unroll
        for (int j = 0; j < 6; j++) acc[i][j] = 0.f;

    for (int k0 = 0; k0 < DI; k0 += 32) {
        float4 av = *(const float4*)(g_xs + (size_t)(row0 + arow) * DI + k0 + acol);
        As[acol + 0][arow] = av.x;
        As[acol + 1][arow] = av.y;
        As[acol + 2][arow] = av.z;
        As[acol + 3][arow] = av.w;
#pragma unroll
        for (int i = 0; i < 6; i++)
            *(float4*)&Bs[brow][bcol + i * 4] =
                *(const float4*)(W + (size_t)(k0 + brow) * NPROJ + bcol + i * 4);
        __syncthreads();
#pragma unroll
        for (int kk = 0; kk < 32; kk++) {
            float2 a2 = *(float2*)&As[kk][ty * 2];
            float b0 = Bs[kk][tx * 6 + 0], b1 = Bs[kk][tx * 6 + 1];
            float b2 = Bs[kk][tx * 6 + 2], b3 = Bs[kk][tx * 6 + 3];
            float b4 = Bs[kk][tx * 6 + 4], b5 = Bs[kk][tx * 6 + 5];
            acc[0][0] = fmaf(a2.x, b0, acc[0][0]);
            acc[0][1] = fmaf(a2.x, b1, acc[0][1]);
            acc[0][2] = fmaf(a2.x, b2, acc[0][2]);
            acc[0][3] = fmaf(a2.x, b3, acc[0][3]);
            acc[0][4] = fmaf(a2.x, b4, acc[0][4]);
            acc[0][5] = fmaf(a2.x, b5, acc[0][5]);
            acc[1][0] = fmaf(a2.y, b0, acc[1][0]);
            acc[1][1] = fmaf(a2.y, b1, acc[1][1]);
            acc[1][2] = fmaf(a2.y, b2, acc[1][2]);
            acc[1][3] = fmaf(a2.y, b3, acc[1][3]);
            acc[1][4] = fmaf(a2.y, b4, acc[1][4]);
            acc[1][5] = fmaf(a2.y, b5, acc[1][5]);
        }
        __syncthreads();
    }
#pragma unroll
    for (int i = 0; i < 2; i++)
#pragma unroll
        for (int j = 0; j < 6; j++)
            g_proj[(size_t)(row0 + ty * 2 + i) * NPROJ + tx * 6 + j] = acc[i][j];
}

// ---------------- selective scan: lane = (channel, n); 2 channels / warp ---
__global__ void __launch_bounds__(256) scan_k(const float* __restrict__ A_log,
                                              const float* __restrict__ Dp) {
    int lane = threadIdx.x & 31;
    int n = lane & 15;
    int half = lane >> 4;
    int warp = threadIdx.x >> 5;
    int c = blockIdx.x * 16 + warp * 2 + half;

    float A = -__expf(A_log[c * NS + n]);
    float Dc = Dp[c];
    float state = 0.f;

    const float* dlt = g_delta + c;
    const float* xsp = g_xs + c;
    const float* rsp = g_res + c;
    float* up = g_u + c;

#pragma unroll 2
    for (int l = 0; l < LSEQ; l++) {
        float d = dlt[(size_t)l * DI];
        float xv = xsp[(size_t)l * DI];
        float Bv = g_proj[(size_t)l * NPROJ + DTR + n];
        float Cv = g_proj[(size_t)l * NPROJ + DTR + NS + n];
        float dA = __expf(d * A);
        state = fmaf(dA, state, d * xv * Bv);
        float y = state * Cv;
        y += __shfl_xor_sync(0xffffffffu, y, 1);
        y += __shfl_xor_sync(0xffffffffu, y, 2);
        y += __shfl_xor_sync(0xffffffffu, y, 4);
        y += __shfl_xor_sync(0xffffffffu, y, 8);
        if (n == 0) {
            float r = rsp[(size_t)l * DI];
            up[(size_t)l * DI] = (fmaf(xv, Dc, y)) * r;
        }
    }
}

// ---------------- launch ----------------------------------------------------
extern "C" void kernel_launch(void* const* d_in, const int* in_sizes, int n_in,
                              void* d_out, int out_size) {
    const float* x          = (const float*)d_in[0];
    const float* norm_scale = (const float*)d_in[1];
    const float* w_in       = (const float*)d_in[2];
    const float* conv_w     = (const float*)d_in[3];
    const float* conv_b     = (const float*)d_in[4];
    const float* A_log      = (const float*)d_in[5];
    const float* Dv         = (const float*)d_in[6];
    const float* w_xproj    = (const float*)d_in[7];
    const float* w_dt       = (const float*)d_in[8];
    const float* b_dt       = (const float*)d_in[9];
    const float* w_out      = (const float*)d_in[10];

    float *hnorm, *h, *proj, *delta, *u;
    cudaGetSymbolAddress((void**)&hnorm, g_hnorm);
    cudaGetSymbolAddress((void**)&h, g_h);
    cudaGetSymbolAddress((void**)&proj, g_proj);
    cudaGetSymbolAddress((void**)&delta, g_delta);
    cudaGetSymbolAddress((void**)&u, g_u);

    // 1. RMSNorm
    rmsnorm_k<<<LSEQ, 256>>>(x, norm_scale);
    // 2. h = hnorm @ w_in  (2048 x 4096 x 1024)
    sgemm_k<0><<<dim3(4 * DM / 128, LSEQ / 128), 256>>>(
        LSEQ, 4 * DM, DM, DM, hnorm, w_in, nullptr, h);
    // 3. causal depthwise conv + silu on xs; silu(res)
    conv_silu_k<<<LSEQ * DI / 256, 256>>>(conv_w, conv_b);
    // 4. proj = xs @ w_xproj  (2048 x 96 x 2048)
    proj_k<<<LSEQ / 16, 128>>>(w_xproj);
    // 5. delta = softplus(proj[:, :64] @ w_dt + b_dt)  (2048 x 2048 x 64)
    sgemm_k<1><<<dim3(DI / 128, LSEQ / 128), 256>>>(
        LSEQ, DI, DTR, NPROJ, proj, w_dt, b_dt, delta);
    // 6. selective scan -> u = (y + xs*D) * res
    scan_k<<<DI / 16, 256>>>(A_log, Dv);
    // 7. out = x + u @ w_out  (2048 x 1024 x 2048)
    sgemm_k<2><<<dim3(DM / 128, LSEQ / 128), 256>>>(
        LSEQ, DM, DI, DI, u, w_out, x, (float*)d_out);
}

// round 4
// speedup vs baseline: 1.4252x; 1.4252x over previous
#include <cuda_runtime.h>
#include <cstdint>
#include <math.h>

#define LSEQ 2048
#define DM   1024
#define DI   2048
#define DTR  64
#define NS   16
#define NPROJ 96   // dt_rank + 2N

// ---------------- scratch (static device allocations; no cudaMalloc) --------
__device__ float g_hnorm[LSEQ * DM];
__device__ float g_h[LSEQ * 4 * DM];       // [xs | res]
__device__ float g_xs[LSEQ * DI];
__device__ float g_res[LSEQ * DI];
__device__ float g_proj[LSEQ * NPROJ];     // [delta_low(64) | B(16) | C(16)]
__device__ float g_delta[LSEQ * DI];
__device__ float g_u[LSEQ * DI];
// transposed (K-major) weights
__device__ float g_w_inT[4 * DM * DM];     // [4096,1024]
__device__ float g_w_outT[DM * DI];        // [1024,2048]
__device__ float g_w_xprojT[128 * DI];     // [128(pad 96),2048]
__device__ float g_w_dtT[DI * DTR];        // [2048,64]

__device__ __forceinline__ float siluf(float x) {
    return x / (1.0f + __expf(-x));
}
__device__ __forceinline__ uint32_t tf32r(float x) {
    uint32_t y;
    asm("cvt.rna.tf32.f32 %0, %1;" : "=r"(y) : "f"(x));
    return y;
}

// ---------------- tf32 HMMA GEMM: 128x128 tile, BK=16, 8 warps (2x4) -------
// C[M,N] = A[M,K] @ B^T where B is K-major [N,K] (pre-transposed).
// EPI 0: plain  1: softplus(acc+bias[col])  2: acc + X[row,col]
// EPI 3: atomicAdd into C for cols < nstore (split-K via blockIdx.z)
#define BK 16
#define SST 20   // smem row stride (16 + 4 pad) -> conflict-free frag loads

template <int EPI>
__global__ void __launch_bounds__(256)
mma_gemm(int K, int lda, int ldb, int ldc, int nstore,
         const float* __restrict__ A, const float* __restrict__ B,
         const float* __restrict__ X, float* __restrict__ C) {
    __shared__ uint32_t As[2][128 * SST];
    __shared__ uint32_t Bs[2][128 * SST];
    int tid = threadIdx.x;
    int wid = tid >> 5, lane = tid & 31;
    int wm = wid & 1;        // 2 warps over M (64 rows each)
    int wn = wid >> 1;       // 4 warps over N (32 cols each)
    int g = lane >> 2, tg = lane & 3;

    const float* Ab = A + (size_t)(blockIdx.y * 128) * lda + (size_t)blockIdx.z * K;
    const float* Bb = B + (size_t)(blockIdx.x * 128) * ldb + (size_t)blockIdx.z * K;

    float c[4][4][4];
#pragma unroll
    for (int i = 0; i < 4; i++)
#pragma unroll
        for (int j = 0; j < 4; j++)
#pragma unroll
            for (int k = 0; k < 4; k++) c[i][j][k] = 0.f;

    const int S = K / BK;
    int r0 = tid >> 2, kq0 = tid & 3;            // t=0: rows 0..63
    int r1 = (tid + 256) >> 2, kq1 = tid & 3;    // t=1: rows 64..127

    // prologue: stage 0 -> buf 0
    {
        float4 a0v = *(const float4*)(Ab + (size_t)r0 * lda + kq0 * 4);
        float4 a1v = *(const float4*)(Ab + (size_t)r1 * lda + kq1 * 4);
        float4 b0v = *(const float4*)(Bb + (size_t)r0 * ldb + kq0 * 4);
        float4 b1v = *(const float4*)(Bb + (size_t)r1 * ldb + kq1 * 4);
        uint4* pa0 = (uint4*)&As[0][r0 * SST + kq0 * 4];
        uint4* pa1 = (uint4*)&As[0][r1 * SST + kq1 * 4];
        uint4* pb0 = (uint4*)&Bs[0][r0 * SST + kq0 * 4];
        uint4* pb1 = (uint4*)&Bs[0][r1 * SST + kq1 * 4];
        *pa0 = make_uint4(tf32r(a0v.x), tf32r(a0v.y), tf32r(a0v.z), tf32r(a0v.w));
        *pa1 = make_uint4(tf32r(a1v.x), tf32r(a1v.y), tf32r(a1v.z), tf32r(a1v.w));
        *pb0 = make_uint4(tf32r(b0v.x), tf32r(b0v.y), tf32r(b0v.z), tf32r(b0v.w));
        *pb1 = make_uint4(tf32r(b1v.x), tf32r(b1v.y), tf32r(b1v.z), tf32r(b1v.w));
    }
    __syncthreads();

    for (int s = 0; s < S; s++) {
        int buf = s & 1;
        float4 a0v, a1v, b0v, b1v;
        const bool more = (s + 1) < S;
        if (more) {
            int k0 = (s + 1) * BK;
            a0v = *(const float4*)(Ab + (size_t)r0 * lda + k0 + kq0 * 4);
            a1v = *(const float4*)(Ab + (size_t)r1 * lda + k0 + kq1 * 4);
            b0v = *(const float4*)(Bb + (size_t)r0 * ldb + k0 + kq0 * 4);
            b1v = *(const float4*)(Bb + (size_t)r1 * ldb + k0 + kq1 * 4);
        }
#pragma unroll
        for (int kk = 0; kk < BK; kk += 8) {
            uint32_t af[4][4], bf[4][2];
#pragma unroll
            for (int mt = 0; mt < 4; mt++) {
                const uint32_t* p = &As[buf][(wm * 64 + mt * 16 + g) * SST + kk + tg];
                af[mt][0] = p[0];
                af[mt][1] = p[8 * SST];
                af[mt][2] = p[4];
                af[mt][3] = p[8 * SST + 4];
            }
#pragma unroll
            for (int nt = 0; nt < 4; nt++) {
                const uint32_t* q = &Bs[buf][(wn * 32 + nt * 8 + g) * SST + kk + tg];
                bf[nt][0] = q[0];
                bf[nt][1] = q[4];
            }
#pragma unroll
            for (int mt = 0; mt < 4; mt++)
#pragma unroll
                for (int nt = 0; nt < 4; nt++) {
                    asm volatile(
                        "mma.sync.aligned.m16n8k8.row.col.f32.tf32.tf32.f32 "
                        "{%0,%1,%2,%3}, {%4,%5,%6,%7}, {%8,%9}, {%0,%1,%2,%3};"
                        : "+f"(c[mt][nt][0]), "+f"(c[mt][nt][1]),
                          "+f"(c[mt][nt][2]), "+f"(c[mt][nt][3])
                        : "r"(af[mt][0]), "r"(af[mt][1]), "r"(af[mt][2]), "r"(af[mt][3]),
                          "r"(bf[nt][0]), "r"(bf[nt][1]));
                }
        }
        if (more) {
            int nb = buf ^ 1;
            *(uint4*)&As[nb][r0 * SST + kq0 * 4] =
                make_uint4(tf32r(a0v.x), tf32r(a0v.y), tf32r(a0v.z), tf32r(a0v.w));
            *(uint4*)&As[nb][r1 * SST + kq1 * 4] =
                make_uint4(tf32r(a1v.x), tf32r(a1v.y), tf32r(a1v.z), tf32r(a1v.w));
            *(uint4*)&Bs[nb][r0 * SST + kq0 * 4] =
                make_uint4(tf32r(b0v.x), tf32r(b0v.y), tf32r(b0v.z), tf32r(b0v.w));
            *(uint4*)&Bs[nb][r1 * SST + kq1 * 4] =
                make_uint4(tf32r(b1v.x), tf32r(b1v.y), tf32r(b1v.z), tf32r(b1v.w));
        }
        __syncthreads();
    }

    // epilogue
#pragma unroll
    for (int mt = 0; mt < 4; mt++) {
        int row = blockIdx.y * 128 + wm * 64 + mt * 16 + g;
#pragma unroll
        for (int nt = 0; nt < 4; nt++) {
            int col = blockIdx.x * 128 + wn * 32 + nt * 8 + tg * 2;
#pragma unroll
            for (int h = 0; h < 2; h++) {
                int r = row + h * 8;
                float v0 = c[mt][nt][h * 2 + 0];
                float v1 = c[mt][nt][h * 2 + 1];
                if (EPI == 1) {
                    v0 += X[col];
                    v1 += X[col + 1];
                    v0 = (v0 > 20.f) ? v0 : log1pf(__expf(v0));
                    v1 = (v1 > 20.f) ? v1 : log1pf(__expf(v1));
                } else if (EPI == 2) {
                    v0 += X[(size_t)r * ldc + col];
                    v1 += X[(size_t)r * ldc + col + 1];
                }
                if (EPI == 3) {
                    if (col < nstore) {
                        atomicAdd(&C[(size_t)r * ldc + col], v0);
                        atomicAdd(&C[(size_t)r * ldc + col + 1], v1);
                    }
                } else {
                    float2 st = make_float2(v0, v1);
                    *(float2*)&C[(size_t)r * ldc + col] = st;
                }
            }
        }
    }
}

// ---------------- weight transpose: out[NOUT,K] from in[K,N] (zero-pad) -----
__global__ void transpose_k(const float* __restrict__ in, float* __restrict__ out,
                            int K, int N, int NOUT) {
    __shared__ float t[32][33];
    int kb = blockIdx.x * 32, nb = blockIdx.y * 32;
    int tx = threadIdx.x, ty = threadIdx.y;  // 32 x 8
#pragma unroll
    for (int i = 0; i < 32; i += 8) {
        int k = kb + ty + i, n = nb + tx;
        t[ty + i][tx] = (n < N) ? in[(size_t)k * N + n] : 0.f;
    }
    __syncthreads();
#pragma unroll
    for (int i = 0; i < 32; i += 8) {
        int n = nb + ty + i, k = kb + tx;
        if (n < NOUT) out[(size_t)n * K + k] = t[tx][ty + i];
    }
}

__global__ void zero_proj_k() {
    int i = blockIdx.x * 256 + threadIdx.x;
    ((float4*)g_proj)[i] = make_float4(0.f, 0.f, 0.f, 0.f);
}

// ---------------- RMSNorm ---------------------------------------------------
__global__ void rmsnorm_k(const float* __restrict__ x,
                          const float* __restrict__ sc) {
    int row = blockIdx.x;
    int t = threadIdx.x;
    float4 v = ((const float4*)(x + (size_t)row * DM))[t];
    float s = v.x * v.x + v.y * v.y + v.z * v.z + v.w * v.w;
#pragma unroll
    for (int o = 16; o; o >>= 1) s += __shfl_xor_sync(0xffffffffu, s, o);
    __shared__ float red[8];
    if ((t & 31) == 0) red[t >> 5] = s;
    __syncthreads();
    float tot = 0.f;
#pragma unroll
    for (int i = 0; i < 8; i++) tot += red[i];
    float inv = rsqrtf(tot * (1.0f / DM) + 1e-5f);
    float4 gsc = ((const float4*)sc)[t];
    float4 o;
    o.x = v.x * inv * gsc.x;
    o.y = v.y * inv * gsc.y;
    o.z = v.z * inv * gsc.z;
    o.w = v.w * inv * gsc.w;
    ((float4*)(g_hnorm + (size_t)row * DM))[t] = o;
}

// ---------------- causal depthwise conv (K=4) + silu; silu(res) ------------
__global__ void conv_silu_k(const float* __restrict__ cw,
                            const float* __restrict__ cb) {
    int idx = blockIdx.x * 256 + threadIdx.x;
    int c = idx & (DI - 1);
    int l = idx >> 11;
    float acc = cb[c];
#pragma unroll
    for (int k = 0; k < 4; k++) {
        int ls = l - 3 + k;
        if (ls >= 0) acc = fmaf(g_h[(size_t)ls * (4 * DM) + c], cw[k * DI + c], acc);
    }
    g_xs[idx] = siluf(acc);
    float r = g_h[(size_t)l * (4 * DM) + DI + c];
    g_res[idx] = siluf(r);
}

// ---------------- selective scan: lane = (channel, n); 2 channels / warp ---
__global__ void __launch_bounds__(256) scan_k(const float* __restrict__ A_log,
                                              const float* __restrict__ Dp) {
    int lane = threadIdx.x & 31;
    int n = lane & 15;
    int half = lane >> 4;
    int warp = threadIdx.x >> 5;
    int c = blockIdx.x * 16 + warp * 2 + half;

    float A = -__expf(A_log[c * NS + n]);
    float Dc = Dp[c];
    float state = 0.f;

    const float* dlt = g_delta + c;
    const float* xsp = g_xs + c;
    const float* rsp = g_res + c;
    float* up = g_u + c;

#pragma unroll 2
    for (int l = 0; l < LSEQ; l++) {
        float d = dlt[(size_t)l * DI];
        float xv = xsp[(size_t)l * DI];
        float Bv = g_proj[(size_t)l * NPROJ + DTR + n];
        float Cv = g_proj[(size_t)l * NPROJ + DTR + NS + n];
        float dA = __expf(d * A);
        state = fmaf(dA, state, d * xv * Bv);
        float y = state * Cv;
        y += __shfl_xor_sync(0xffffffffu, y, 1);
        y += __shfl_xor_sync(0xffffffffu, y, 2);
        y += __shfl_xor_sync(0xffffffffu, y, 4);
        y += __shfl_xor_sync(0xffffffffu, y, 8);
        if (n == 0) {
            float r = rsp[(size_t)l * DI];
            up[(size_t)l * DI] = (fmaf(xv, Dc, y)) * r;
        }
    }
}

// ---------------- launch ----------------------------------------------------
extern "C" void kernel_launch(void* const* d_in, const int* in_sizes, int n_in,
                              void* d_out, int out_size) {
    const float* x          = (const float*)d_in[0];
    const float* norm_scale = (const float*)d_in[1];
    const float* w_in       = (const float*)d_in[2];
    const float* conv_w     = (const float*)d_in[3];
    const float* conv_b     = (const float*)d_in[4];
    const float* A_log      = (const float*)d_in[5];
    const float* Dv         = (const float*)d_in[6];
    const float* w_xproj    = (const float*)d_in[7];
    const float* w_dt       = (const float*)d_in[8];
    const float* b_dt       = (const float*)d_in[9];
    const float* w_out      = (const float*)d_in[10];

    float *hnorm, *h, *xs, *proj, *delta, *u;
    float *w_inT, *w_outT, *w_xprojT, *w_dtT;
    cudaGetSymbolAddress((void**)&hnorm, g_hnorm);
    cudaGetSymbolAddress((void**)&h, g_h);
    cudaGetSymbolAddress((void**)&xs, g_xs);
    cudaGetSymbolAddress((void**)&proj, g_proj);
    cudaGetSymbolAddress((void**)&delta, g_delta);
    cudaGetSymbolAddress((void**)&u, g_u);
    cudaGetSymbolAddress((void**)&w_inT, g_w_inT);
    cudaGetSymbolAddress((void**)&w_outT, g_w_outT);
    cudaGetSymbolAddress((void**)&w_xprojT, g_w_xprojT);
    cudaGetSymbolAddress((void**)&w_dtT, g_w_dtT);

    dim3 t32x8(32, 8);
    // weight transposes (K-major B for mma, x-proj zero-padded to 128 rows)
    transpose_k<<<dim3(DM / 32, 4 * DM / 32), t32x8>>>(w_in, w_inT, DM, 4 * DM, 4 * DM);
    transpose_k<<<dim3(DI / 32, DM / 32), t32x8>>>(w_out, w_outT, DI, DM, DM);
    transpose_k<<<dim3(DI / 32, 128 / 32), t32x8>>>(w_xproj, w_xprojT, DI, NPROJ, 128);
    transpose_k<<<dim3(DTR / 32, DI / 32), t32x8>>>(w_dt, w_dtT, DTR, DI, DI);

    // 1. RMSNorm (+ zero split-K accumulator for proj)
    rmsnorm_k<<<LSEQ, 256>>>(x, norm_scale);
    zero_proj_k<<<LSEQ * NPROJ / 4 / 256, 256>>>();
    // 2. h = hnorm @ w_in   (2048 x 4096 x 1024)
    mma_gemm<0><<<dim3(4 * DM / 128, LSEQ / 128), 256>>>(
        DM, DM, DM, 4 * DM, 4 * DM, hnorm, w_inT, nullptr, h);
    // 3. conv + silu
    conv_silu_k<<<LSEQ * DI / 256, 256>>>(conv_w, conv_b);
    // 4. proj = xs @ w_xproj  (2048 x 96[pad128] x 2048), split-K=8
    mma_gemm<3><<<dim3(1, LSEQ / 128, 8), 256>>>(
        DI / 8, DI, DI, NPROJ, NPROJ, xs, w_xprojT, nullptr, proj);
    // 5. delta = softplus(proj[:, :64] @ w_dt + b_dt)  (2048 x 2048 x 64)
    mma_gemm<1><<<dim3(DI / 128, LSEQ / 128), 256>>>(
        DTR, NPROJ, DTR, DI, DI, proj, w_dtT, b_dt, delta);
    // 6. selective scan
    scan_k<<<DI / 16, 256>>>(A_log, Dv);
    // 7. out = x + u @ w_out  (2048 x 1024 x 2048)
    mma_gemm<2><<<dim3(DM / 128, LSEQ / 128), 256>>>(
        DI, DI, DI, DM, DM, u, w_outT, x, (float*)d_out);
}

// round 6
// speedup vs baseline: 2.1321x; 1.4960x over previous
#include <cuda_runtime.h>
#include <cuda_bf16.h>
#include <cuda_fp16.h>
#include <cstdint>
#include <math.h>

#define LSEQ 2048
#define DM   1024
#define DI   2048
#define DTR  64
#define NS   16
#define NPROJ 96   // dt_rank + 2N

// ---------------- scratch (static device allocations; no cudaMalloc) --------
__device__ __nv_bfloat16 g_hnormb[LSEQ * DM];     // rmsnorm out (bf16)
__device__ float g_h[LSEQ * 4 * DM];              // [xs | res] fp32
__device__ float g_xs[LSEQ * DI];                 // fp32 (scan)
__device__ __nv_bfloat16 g_xsb[LSEQ * DI];        // bf16 (proj GEMM)
__device__ float g_res[LSEQ * DI];
__device__ float g_proj[LSEQ * NPROJ];            // [delta_low(64) | B(16) | C(16)]
__device__ float g_delta[LSEQ * DI];
__device__ __nv_bfloat16 g_ub[LSEQ * DI];         // scan out (bf16, feeds out-proj)
// K-major weights
__device__ __nv_bfloat16 g_w_inT[4 * DM * DM];    // [4096,1024] bf16
__device__ __nv_bfloat16 g_w_outT[DM * DI];       // [1024,2048] bf16
__device__ __nv_bfloat16 g_w_xprojT[128 * DI];    // [128(pad 96),2048] bf16
__device__ float g_w_dtT[DI * DTR];               // [2048,64] fp32 (tf32 path)

__device__ __forceinline__ float siluf(float x) {
    return x / (1.0f + __expf(-x));
}
__device__ __forceinline__ uint32_t tf32r(float x) {
    uint32_t y;
    asm("cvt.rna.tf32.f32 %0, %1;" : "=r"(y) : "f"(x));
    return y;
}

// ============ bf16 HMMA GEMM: 128x128 tile, BK=32, 8 warps (2x4) ============
// C[M,N] = A[M,K] @ B^T, A and B both bf16 K-major.
// EPI 0: plain  2: acc + X[row,col]  3: atomicAdd into C for cols < nstore
#define BSTH 40  // halfs per smem row (32 + 8 pad) -> conflict-free frag LDS

template <int EPI>
__global__ void __launch_bounds__(256)
bgemm(int K, int lda, int ldb, int ldc, int nstore,
      const __nv_bfloat16* __restrict__ A, const __nv_bfloat16* __restrict__ B,
      const float* __restrict__ X, float* __restrict__ C) {
    __shared__ __nv_bfloat16 As[2][128 * BSTH];
    __shared__ __nv_bfloat16 Bs[2][128 * BSTH];
    int tid = threadIdx.x;
    int wid = tid >> 5, lane = tid & 31;
    int wm = wid & 1;        // 2 warps over M (64 rows each)
    int wn = wid >> 1;       // 4 warps over N (32 cols each)
    int g = lane >> 2, tg = lane & 3;

    const __nv_bfloat16* Ab = A + (size_t)(blockIdx.y * 128) * lda + (size_t)blockIdx.z * K;
    const __nv_bfloat16* Bb = B + (size_t)(blockIdx.x * 128) * ldb + (size_t)blockIdx.z * K;

    float c[4][4][4];
#pragma unroll
    for (int i = 0; i < 4; i++)
#pragma unroll
        for (int j = 0; j < 4; j++)
#pragma unroll
            for (int k = 0; k < 4; k++) c[i][j][k] = 0.f;

    const int S = K / 32;
    int r = tid >> 1;            // 0..127
    int hb = (tid & 1) * 16;     // col-half (16 bf16 = 32B)

    // prologue -> buf 0
    {
        const __nv_bfloat16* pa = Ab + (size_t)r * lda + hb;
        const __nv_bfloat16* pb = Bb + (size_t)r * ldb + hb;
        *(uint4*)&As[0][r * BSTH + hb]     = *(const uint4*)pa;
        *(uint4*)&As[0][r * BSTH + hb + 8] = *(const uint4*)(pa + 8);
        *(uint4*)&Bs[0][r * BSTH + hb]     = *(const uint4*)pb;
        *(uint4*)&Bs[0][r * BSTH + hb + 8] = *(const uint4*)(pb + 8);
    }
    __syncthreads();

    for (int s = 0; s < S; s++) {
        int buf = s & 1;
        uint4 va0, va1, vb0, vb1;
        const bool more = (s + 1) < S;
        if (more) {
            const __nv_bfloat16* pa = Ab + (size_t)r * lda + (s + 1) * 32 + hb;
            const __nv_bfloat16* pb = Bb + (size_t)r * ldb + (s + 1) * 32 + hb;
            va0 = *(const uint4*)pa;
            va1 = *(const uint4*)(pa + 8);
            vb0 = *(const uint4*)pb;
            vb1 = *(const uint4*)(pb + 8);
        }
#pragma unroll
        for (int kk = 0; kk < 32; kk += 16) {
            uint32_t af[4][4], bf[4][2];
#pragma unroll
            for (int mt = 0; mt < 4; mt++) {
                const __nv_bfloat16* p = &As[buf][(wm * 64 + mt * 16 + g) * BSTH + kk + 2 * tg];
                af[mt][0] = *(const uint32_t*)(p);
                af[mt][1] = *(const uint32_t*)(p + 8 * BSTH);
                af[mt][2] = *(const uint32_t*)(p + 8);
                af[mt][3] = *(const uint32_t*)(p + 8 * BSTH + 8);
            }
#pragma unroll
            for (int nt = 0; nt < 4; nt++) {
                const __nv_bfloat16* q = &Bs[buf][(wn * 32 + nt * 8 + g) * BSTH + kk + 2 * tg];
                bf[nt][0] = *(const uint32_t*)(q);
                bf[nt][1] = *(const uint32_t*)(q + 8);
            }
#pragma unroll
            for (int mt = 0; mt < 4; mt++)
#pragma unroll
                for (int nt = 0; nt < 4; nt++) {
                    asm volatile(
                        "mma.sync.aligned.m16n8k16.row.col.f32.bf16.bf16.f32 "
                        "{%0,%1,%2,%3}, {%4,%5,%6,%7}, {%8,%9}, {%0,%1,%2,%3};"
                        : "+f"(c[mt][nt][0]), "+f"(c[mt][nt][1]),
                          "+f"(c[mt][nt][2]), "+f"(c[mt][nt][3])
                        : "r"(af[mt][0]), "r"(af[mt][1]), "r"(af[mt][2]), "r"(af[mt][3]),
                          "r"(bf[nt][0]), "r"(bf[nt][1]));
                }
        }
        if (more) {
            int nb = buf ^ 1;
            *(uint4*)&As[nb][r * BSTH + hb]     = va0;
            *(uint4*)&As[nb][r * BSTH + hb + 8] = va1;
            *(uint4*)&Bs[nb][r * BSTH + hb]     = vb0;
            *(uint4*)&Bs[nb][r * BSTH + hb + 8] = vb1;
        }
        __syncthreads();
    }

#pragma unroll
    for (int mt = 0; mt < 4; mt++) {
        int row = blockIdx.y * 128 + wm * 64 + mt * 16 + g;
#pragma unroll
        for (int nt = 0; nt < 4; nt++) {
            int col = blockIdx.x * 128 + wn * 32 + nt * 8 + tg * 2;
#pragma unroll
            for (int h = 0; h < 2; h++) {
                int rr = row + h * 8;
                float v0 = c[mt][nt][h * 2 + 0];
                float v1 = c[mt][nt][h * 2 + 1];
                if (EPI == 2) {
                    v0 += X[(size_t)rr * ldc + col];
                    v1 += X[(size_t)rr * ldc + col + 1];
                }
                if (EPI == 3) {
                    if (col < nstore) {
                        atomicAdd(&C[(size_t)rr * ldc + col], v0);
                        atomicAdd(&C[(size_t)rr * ldc + col + 1], v1);
                    }
                } else {
                    *(float2*)&C[(size_t)rr * ldc + col] = make_float2(v0, v1);
                }
            }
        }
    }
}

// ============ tf32 HMMA GEMM (delta path only), BK=16 =======================
#define BK 16
#define SST 20

__global__ void __launch_bounds__(256)
mma_gemm_sp(int K, int lda, int ldb, int ldc,
            const float* __restrict__ A, const float* __restrict__ B,
            const float* __restrict__ X, float* __restrict__ C) {
    __shared__ uint32_t As[2][128 * SST];
    __shared__ uint32_t Bs[2][128 * SST];
    int tid = threadIdx.x;
    int wid = tid >> 5, lane = tid & 31;
    int wm = wid & 1, wn = wid >> 1;
    int g = lane >> 2, tg = lane & 3;

    const float* Ab = A + (size_t)(blockIdx.y * 128) * lda;
    const float* Bb = B + (size_t)(blockIdx.x * 128) * ldb;

    float c[4][4][4];
#pragma unroll
    for (int i = 0; i < 4; i++)
#pragma unroll
        for (int j = 0; j < 4; j++)
#pragma unroll
            for (int k = 0; k < 4; k++) c[i][j][k] = 0.f;

    const int S = K / BK;
    int r0 = tid >> 2, kq0 = tid & 3;
    int r1 = (tid + 256) >> 2, kq1 = tid & 3;

    {
        float4 a0v = *(const float4*)(Ab + (size_t)r0 * lda + kq0 * 4);
        float4 a1v = *(const float4*)(Ab + (size_t)r1 * lda + kq1 * 4);
        float4 b0v = *(const float4*)(Bb + (size_t)r0 * ldb + kq0 * 4);
        float4 b1v = *(const float4*)(Bb + (size_t)r1 * ldb + kq1 * 4);
        *(uint4*)&As[0][r0 * SST + kq0 * 4] =
            make_uint4(tf32r(a0v.x), tf32r(a0v.y), tf32r(a0v.z), tf32r(a0v.w));
        *(uint4*)&As[0][r1 * SST + kq1 * 4] =
            make_uint4(tf32r(a1v.x), tf32r(a1v.y), tf32r(a1v.z), tf32r(a1v.w));
        *(uint4*)&Bs[0][r0 * SST + kq0 * 4] =
            make_uint4(tf32r(b0v.x), tf32r(b0v.y), tf32r(b0v.z), tf32r(b0v.w));
        *(uint4*)&Bs[0][r1 * SST + kq1 * 4] =
            make_uint4(tf32r(b1v.x), tf32r(b1v.y), tf32r(b1v.z), tf32r(b1v.w));
    }
    __syncthreads();

    for (int s = 0; s < S; s++) {
        int buf = s & 1;
        float4 a0v, a1v, b0v, b1v;
        const bool more = (s + 1) < S;
        if (more) {
            int k0 = (s + 1) * BK;
            a0v = *(const float4*)(Ab + (size_t)r0 * lda + k0 + kq0 * 4);
            a1v = *(const float4*)(Ab + (size_t)r1 * lda + k0 + kq1 * 4);
            b0v = *(const float4*)(Bb + (size_t)r0 * ldb + k0 + kq0 * 4);
            b1v = *(const float4*)(Bb + (size_t)r1 * ldb + k0 + kq1 * 4);
        }
#pragma unroll
        for (int kk = 0; kk < BK; kk += 8) {
            uint32_t af[4][4], bf[4][2];
#pragma unroll
            for (int mt = 0; mt < 4; mt++) {
                const uint32_t* p = &As[buf][(wm * 64 + mt * 16 + g) * SST + kk + tg];
                af[mt][0] = p[0];
                af[mt][1] = p[8 * SST];
                af[mt][2] = p[4];
                af[mt][3] = p[8 * SST + 4];
            }
#pragma unroll
            for (int nt = 0; nt < 4; nt++) {
                const uint32_t* q = &Bs[buf][(wn * 32 + nt * 8 + g) * SST + kk + tg];
                bf[nt][0] = q[0];
                bf[nt][1] = q[4];
            }
#pragma unroll
            for (int mt = 0; mt < 4; mt++)
#pragma unroll
                for (int nt = 0; nt < 4; nt++) {
                    asm volatile(
                        "mma.sync.aligned.m16n8k8.row.col.f32.tf32.tf32.f32 "
                        "{%0,%1,%2,%3}, {%4,%5,%6,%7}, {%8,%9}, {%0,%1,%2,%3};"
                        : "+f"(c[mt][nt][0]), "+f"(c[mt][nt][1]),
                          "+f"(c[mt][nt][2]), "+f"(c[mt][nt][3])
                        : "r"(af[mt][0]), "r"(af[mt][1]), "r"(af[mt][2]), "r"(af[mt][3]),
                          "r"(bf[nt][0]), "r"(bf[nt][1]));
                }
        }
        if (more) {
            int nb = buf ^ 1;
            *(uint4*)&As[nb][r0 * SST + kq0 * 4] =
                make_uint4(tf32r(a0v.x), tf32r(a0v.y), tf32r(a0v.z), tf32r(a0v.w));
            *(uint4*)&As[nb][r1 * SST + kq1 * 4] =
                make_uint4(tf32r(a1v.x), tf32r(a1v.y), tf32r(a1v.z), tf32r(a1v.w));
            *(uint4*)&Bs[nb][r0 * SST + kq0 * 4] =
                make_uint4(tf32r(b0v.x), tf32r(b0v.y), tf32r(b0v.z), tf32r(b0v.w));
            *(uint4*)&Bs[nb][r1 * SST + kq1 * 4] =
                make_uint4(tf32r(b1v.x), tf32r(b1v.y), tf32r(b1v.z), tf32r(b1v.w));
        }
        __syncthreads();
    }

    // epilogue: softplus(acc + bias[col])
#pragma unroll
    for (int mt = 0; mt < 4; mt++) {
        int row = blockIdx.y * 128 + wm * 64 + mt * 16 + g;
#pragma unroll
        for (int nt = 0; nt < 4; nt++) {
            int col = blockIdx.x * 128 + wn * 32 + nt * 8 + tg * 2;
#pragma unroll
            for (int h = 0; h < 2; h++) {
                int rr = row + h * 8;
                float v0 = c[mt][nt][h * 2 + 0] + X[col];
                float v1 = c[mt][nt][h * 2 + 1] + X[col + 1];
                v0 = (v0 > 20.f) ? v0 : log1pf(__expf(v0));
                v1 = (v1 > 20.f) ? v1 : log1pf(__expf(v1));
                *(float2*)&C[(size_t)rr * ldc + col] = make_float2(v0, v1);
            }
        }
    }
}

// ---------------- weight transposes ------------------------------------------
__global__ void transpose_bf(const float* __restrict__ in, __nv_bfloat16* __restrict__ out,
                             int K, int N, int NOUT) {
    __shared__ float t[32][33];
    int kb = blockIdx.x * 32, nb = blockIdx.y * 32;
    int tx = threadIdx.x, ty = threadIdx.y;  // 32 x 8
#pragma unroll
    for (int i = 0; i < 32; i += 8) {
        int k = kb + ty + i, n = nb + tx;
        t[ty + i][tx] = (n < N) ? in[(size_t)k * N + n] : 0.f;
    }
    __syncthreads();
#pragma unroll
    for (int i = 0; i < 32; i += 8) {
        int n = nb + ty + i, k = kb + tx;
        if (n < NOUT) out[(size_t)n * K + k] = __float2bfloat16_rn(t[tx][ty + i]);
    }
}
__global__ void transpose_f32(const float* __restrict__ in, float* __restrict__ out,
                              int K, int N) {
    __shared__ float t[32][33];
    int kb = blockIdx.x * 32, nb = blockIdx.y * 32;
    int tx = threadIdx.x, ty = threadIdx.y;
#pragma unroll
    for (int i = 0; i < 32; i += 8)
        t[ty + i][tx] = in[(size_t)(kb + ty + i) * N + nb + tx];
    __syncthreads();
#pragma unroll
    for (int i = 0; i < 32; i += 8)
        out[(size_t)(nb + ty + i) * K + kb + tx] = t[tx][ty + i];
}

__global__ void zero_proj_k() {
    int i = blockIdx.x * 256 + threadIdx.x;
    ((float4*)g_proj)[i] = make_float4(0.f, 0.f, 0.f, 0.f);
}

// ---------------- RMSNorm (writes bf16) -------------------------------------
__global__ void rmsnorm_k(const float* __restrict__ x,
                          const float* __restrict__ sc) {
    int row = blockIdx.x;
    int t = threadIdx.x;
    float4 v = ((const float4*)(x + (size_t)row * DM))[t];
    float s = v.x * v.x + v.y * v.y + v.z * v.z + v.w * v.w;
#pragma unroll
    for (int o = 16; o; o >>= 1) s += __shfl_xor_sync(0xffffffffu, s, o);
    __shared__ float red[8];
    if ((t & 31) == 0) red[t >> 5] = s;
    __syncthreads();
    float tot = 0.f;
#pragma unroll
    for (int i = 0; i < 8; i++) tot += red[i];
    float inv = rsqrtf(tot * (1.0f / DM) + 1e-5f);
    float4 gsc = ((const float4*)sc)[t];
    __nv_bfloat162 p0, p1;
    p0.x = __float2bfloat16_rn(v.x * inv * gsc.x);
    p0.y = __float2bfloat16_rn(v.y * inv * gsc.y);
    p1.x = __float2bfloat16_rn(v.z * inv * gsc.z);
    p1.y = __float2bfloat16_rn(v.w * inv * gsc.w);
    ((__nv_bfloat162*)(g_hnormb + (size_t)row * DM))[t * 2] = p0;
    ((__nv_bfloat162*)(g_hnormb + (size_t)row * DM))[t * 2 + 1] = p1;
}

// ---------------- causal depthwise conv (K=4) + silu ------------------------
__global__ void conv_silu_k(const float* __restrict__ cw,
                            const float* __restrict__ cb) {
    int idx = blockIdx.x * 256 + threadIdx.x;
    int c = idx & (DI - 1);
    int l = idx >> 11;
    float acc = cb[c];
#pragma unroll
    for (int k = 0; k < 4; k++) {
        int ls = l - 3 + k;
        if (ls >= 0) acc = fmaf(g_h[(size_t)ls * (4 * DM) + c], cw[k * DI + c], acc);
    }
    float xs = siluf(acc);
    g_xs[idx] = xs;
    g_xsb[idx] = __float2bfloat16_rn(xs);
    float r = g_h[(size_t)l * (4 * DM) + DI + c];
    g_res[idx] = siluf(r);
}

// ---------------- selective scan: fp16x2 exp2, 2 timesteps per MUFU op ------
__global__ void __launch_bounds__(256) scan_k(const float* __restrict__ A_log,
                                              const float* __restrict__ Dp) {
    int lane = threadIdx.x & 31;
    int n = lane & 15;
    int half = lane >> 4;
    int warp = threadIdx.x >> 5;
    int c = blockIdx.x * 16 + warp * 2 + half;

    // fold log2(e) so decay = exp2(d * Ah)
    float Ah = -__expf(A_log[c * NS + n]) * 1.44269504f;
    float Dc = Dp[c];
    float state = 0.f;

    const float* dlt = g_delta + c;
    const float* xsp = g_xs + c;
    const float* rsp = g_res + c;
    __nv_bfloat16* up = g_ub + c;

#pragma unroll 2
    for (int l = 0; l < LSEQ; l += 2) {
        float d0 = dlt[(size_t)l * DI];
        float d1 = dlt[(size_t)(l + 1) * DI];
        float x0 = xsp[(size_t)l * DI];
        float x1 = xsp[(size_t)(l + 1) * DI];
        float B0 = g_proj[(size_t)l * NPROJ + DTR + n];
        float B1 = g_proj[(size_t)(l + 1) * NPROJ + DTR + n];
        float C0 = g_proj[(size_t)l * NPROJ + DTR + NS + n];
        float C1 = g_proj[(size_t)(l + 1) * NPROJ + DTR + NS + n];

        __half2 hh = h2exp2(__floats2half2_rn(d0 * Ah, d1 * Ah));
        float dA0 = __low2float(hh);
        float dA1 = __high2float(hh);

        state = fmaf(dA0, state, d0 * x0 * B0);
        float y0 = state * C0;
        state = fmaf(dA1, state, d1 * x1 * B1);
        float y1 = state * C1;

        y0 += __shfl_xor_sync(0xffffffffu, y0, 1);
        y1 += __shfl_xor_sync(0xffffffffu, y1, 1);
        y0 += __shfl_xor_sync(0xffffffffu, y0, 2);
        y1 += __shfl_xor_sync(0xffffffffu, y1, 2);
        y0 += __shfl_xor_sync(0xffffffffu, y0, 4);
        y1 += __shfl_xor_sync(0xffffffffu, y1, 4);
        y0 += __shfl_xor_sync(0xffffffffu, y0, 8);
        y1 += __shfl_xor_sync(0xffffffffu, y1, 8);

        if (n == 0) {
            float r0 = rsp[(size_t)l * DI];
            float r1 = rsp[(size_t)(l + 1) * DI];
            up[(size_t)l * DI] = __float2bfloat16_rn(fmaf(x0, Dc, y0) * r0);
            up[(size_t)(l + 1) * DI] = __float2bfloat16_rn(fmaf(x1, Dc, y1) * r1);
        }
    }
}

// ---------------- launch ----------------------------------------------------
extern "C" void kernel_launch(void* const* d_in, const int* in_sizes, int n_in,
                              void* d_out, int out_size) {
    const float* x          = (const float*)d_in[0];
    const float* norm_scale = (const float*)d_in[1];
    const float* w_in       = (const float*)d_in[2];
    const float* conv_w     = (const float*)d_in[3];
    const float* conv_b     = (const float*)d_in[4];
    const float* A_log      = (const float*)d_in[5];
    const float* Dv         = (const float*)d_in[6];
    const float* w_xproj    = (const float*)d_in[7];
    const float* w_dt       = (const float*)d_in[8];
    const float* b_dt       = (const float*)d_in[9];
    const float* w_out      = (const float*)d_in[10];

    __nv_bfloat16 *hnormb, *xsb, *ub, *w_inT, *w_outT, *w_xprojT;
    float *h, *proj, *delta, *w_dtT;
    cudaGetSymbolAddress((void**)&hnormb, g_hnormb);
    cudaGetSymbolAddress((void**)&h, g_h);
    cudaGetSymbolAddress((void**)&xsb, g_xsb);
    cudaGetSymbolAddress((void**)&proj, g_proj);
    cudaGetSymbolAddress((void**)&delta, g_delta);
    cudaGetSymbolAddress((void**)&ub, g_ub);
    cudaGetSymbolAddress((void**)&w_inT, g_w_inT);
    cudaGetSymbolAddress((void**)&w_outT, g_w_outT);
    cudaGetSymbolAddress((void**)&w_xprojT, g_w_xprojT);
    cudaGetSymbolAddress((void**)&w_dtT, g_w_dtT);

    dim3 t32x8(32, 8);
    // launches 0-4
    transpose_bf<<<dim3(DM / 32, 4 * DM / 32), t32x8>>>(w_in, w_inT, DM, 4 * DM, 4 * DM);
    rmsnorm_k<<<LSEQ, 256>>>(x, norm_scale);
    transpose_bf<<<dim3(DI / 32, DM / 32), t32x8>>>(w_out, w_outT, DI, DM, DM);
    transpose_bf<<<dim3(DI / 32, 128 / 32), t32x8>>>(w_xproj, w_xprojT, DI, NPROJ, 128);
    transpose_f32<<<dim3(DTR / 32, DI / 32), t32x8>>>(w_dt, w_dtT, DTR, DI);
    // launch 5 (ncu capture slot): h = hnorm @ w_in  (2048 x 4096 x 1024)
    bgemm<0><<<dim3(4 * DM / 128, LSEQ / 128), 256>>>(
        DM, DM, DM, 4 * DM, 4 * DM, hnormb, w_inT, nullptr, h);
    zero_proj_k<<<LSEQ * NPROJ / 4 / 256, 256>>>();
    conv_silu_k<<<LSEQ * DI / 256, 256>>>(conv_w, conv_b);
    // proj = xs @ w_xproj  (2048 x 96[pad128] x 2048), split-K=8
    bgemm<3><<<dim3(1, LSEQ / 128, 8), 256>>>(
        DI / 8, DI, DI, NPROJ, NPROJ, xsb, w_xprojT, nullptr, proj);
    // delta = softplus(proj[:, :64] @ w_dt + b_dt)  (tf32)
    mma_gemm_sp<<<dim3(DI / 128, LSEQ / 128), 256>>>(
        DTR, NPROJ, DTR, DI, proj, w_dtT, b_dt, delta);
    // selective scan
    scan_k<<<DI / 16, 256>>>(A_log, Dv);
    // out = x + u @ w_out  (2048 x 1024 x 2048)
    bgemm<2><<<dim3(DM / 128, LSEQ / 128), 256>>>(
        DI, DI, DI, DM, DM, ub, w_outT, x, (float*)d_out);
}